// round 2
// baseline (speedup 1.0000x reference)
#include <cuda_runtime.h>
#include <cstdint>

#define BB   32
#define NN   512
#define FIN  128
#define FH   64
#define NH   8
#define FC   512      // NH*FH
#define CC   16
#define NEGINF (-9e15f)
#define LALPHA 0.2f
#define JB   128

// ---------------- device scratch (allocation-free rule: __device__ globals) ----
__device__ float g_hfeat[BB*NN*FC];          // layer1 projected features [b][n][h*64+o]
__device__ float g_xcat [BB*NN*FC];          // layer1 output (ELU'd, concat)  [b][n][h*64+o]
__device__ unsigned int g_mask[BB*NN*(NN/32)]; // adj bitmask, 16 words per row
__device__ float g_f1[NH*BB*NN], g_f2[NH*BB*NN];
__device__ float g_h2[BB*NN*CC];
__device__ float g_f1b[BB*NN], g_f2b[BB*NN];

// ---------------- packed f32x2 helpers ----------------------------------------
__device__ __forceinline__ unsigned long long pack2(float x, float y){
    unsigned long long r; asm("mov.b64 %0, {%1, %2};" : "=l"(r) : "f"(x), "f"(y)); return r;
}
__device__ __forceinline__ float2 unpack2(unsigned long long v){
    float2 r; asm("mov.b64 {%0, %1}, %2;" : "=f"(r.x), "=f"(r.y) : "l"(v)); return r;
}
__device__ __forceinline__ unsigned long long fma2(unsigned long long a, unsigned long long b, unsigned long long c){
    unsigned long long d; asm("fma.rn.f32x2 %0, %1, %2, %3;" : "=l"(d) : "l"(a), "l"(b), "l"(c)); return d;
}
__device__ __forceinline__ unsigned long long mul2(unsigned long long a, unsigned long long b){
    unsigned long long d; asm("mul.rn.f32x2 %0, %1, %2;" : "=l"(d) : "l"(a), "l"(b)); return d;
}

// ---------------- kernel 1: pack adj into bitmask ------------------------------
__global__ __launch_bounds__(256) void pack_mask_kernel(const int* __restrict__ adj){
    int gw   = (blockIdx.x * 256 + threadIdx.x) >> 5;   // global warp id, 0..262143
    int lane = threadIdx.x & 31;
    int w = gw & 15;
    int n = (gw >> 4) & 511;
    int b = gw >> 13;
    int v = adj[((size_t)(b*NN + n))*NN + w*32 + lane];
    unsigned int bits = __ballot_sync(0xffffffffu, v > 0);
    if (lane == 0) g_mask[(b*NN + n)*16 + w] = bits;
}

// ---------------- kernel 2: layer1 projection GEMM  hfeat = x @ W --------------
// M = 16384, K = 128, per-head N = 64.  BM=128, BN=64 (one head per block.y)
__global__ __launch_bounds__(256) void proj1_kernel(const float* __restrict__ X,
                                                    const float* __restrict__ Wh){
    __shared__ float As[16][132];                  // [k][m], padded
    __shared__ unsigned long long Bs[16][32];      // [k][n/2]
    const int tid = threadIdx.x;
    const int m0  = blockIdx.x * 128;
    const int h   = blockIdx.y;
    const int tx  = tid & 15;     // 16 col groups of 4
    const int ty  = tid >> 4;     // 16 row groups of 8

    unsigned long long acc[8][2];
#pragma unroll
    for (int i = 0; i < 8; i++){ acc[i][0] = 0ull; acc[i][1] = 0ull; }

    for (int k0 = 0; k0 < FIN; k0 += 16){
        __syncthreads();
        // A tile: 128 rows x 16 k  = 512 float4
#pragma unroll
        for (int i = 0; i < 2; i++){
            int lin = tid + i*256;
            int mm  = lin >> 2;
            int kq  = lin & 3;
            float4 v = *(const float4*)&X[(size_t)(m0 + mm)*FIN + k0 + kq*4];
            As[kq*4+0][mm] = v.x; As[kq*4+1][mm] = v.y;
            As[kq*4+2][mm] = v.z; As[kq*4+3][mm] = v.w;
        }
        // B tile: 16 k x 64 cols
        {
            int k  = tid >> 4;
            int cq = tid & 15;
            float4 v = *(const float4*)&Wh[(size_t)(h*FIN + k0 + k)*FH + cq*4];
            ((float4*)&Bs[k][0])[cq] = v;
        }
        __syncthreads();
#pragma unroll
        for (int k = 0; k < 16; k++){
            float4 a0 = *(const float4*)&As[k][ty*8];
            float4 a1 = *(const float4*)&As[k][ty*8 + 4];
            ulonglong2 bp = *(const ulonglong2*)&Bs[k][tx*2];
            float av[8] = {a0.x,a0.y,a0.z,a0.w,a1.x,a1.y,a1.z,a1.w};
#pragma unroll
            for (int i = 0; i < 8; i++){
                unsigned long long aa = pack2(av[i], av[i]);
                acc[i][0] = fma2(aa, bp.x, acc[i][0]);
                acc[i][1] = fma2(aa, bp.y, acc[i][1]);
            }
        }
    }
#pragma unroll
    for (int i = 0; i < 8; i++){
        int row = m0 + ty*8 + i;
        float2 v0 = unpack2(acc[i][0]);
        float2 v1 = unpack2(acc[i][1]);
        float4 o4 = make_float4(v0.x, v0.y, v1.x, v1.y);
        *(float4*)&g_hfeat[(size_t)row*FC + h*FH + tx*4] = o4;
    }
}

// ---------------- kernel 3: per-head score vectors f1, f2 ----------------------
__global__ __launch_bounds__(256) void fvec1_kernel(const float* __restrict__ a1h,
                                                    const float* __restrict__ a2h){
    __shared__ float a1s[NH*FH], a2s[NH*FH];
    const int tid = threadIdx.x;
#pragma unroll
    for (int i = 0; i < 2; i++){
        a1s[tid + i*256] = a1h[tid + i*256];
        a2s[tid + i*256] = a2h[tid + i*256];
    }
    __syncthreads();
    int t = blockIdx.x * 256 + tid;   // 0..131071
    int h = t & 7;
    int n = (t >> 3) & 511;
    int b = t >> 12;
    const float4* hr = (const float4*)&g_hfeat[(size_t)(b*NN + n)*FC + h*FH];
    float s1 = 0.f, s2 = 0.f;
#pragma unroll
    for (int o4 = 0; o4 < 16; o4++){
        float4 v = hr[o4];
        int base = h*FH + o4*4;
        s1 += v.x*a1s[base] + v.y*a1s[base+1] + v.z*a1s[base+2] + v.w*a1s[base+3];
        s2 += v.x*a2s[base] + v.y*a2s[base+1] + v.z*a2s[base+2] + v.w*a2s[base+3];
    }
    g_f1[(h*BB + b)*NN + n] = s1;
    g_f2[(h*BB + b)*NN + n] = s2;
}

// ---------------- kernel 4: layer1 fused masked-softmax attention (hot) --------
// One thread = one query row.  Flash-style online softmax; PV accumulate in
// packed f32x2.  grid = (N/256, B, H), 256 threads.
__global__ __launch_bounds__(256, 2) void attn1_kernel(){
    __shared__ unsigned long long hs[JB][FH/2];   // key tile [j][o2]
    __shared__ float f2s[JB];
    const int tid = threadIdx.x;
    const int b = blockIdx.y, h = blockIdx.z;
    const int q = blockIdx.x * 256 + tid;

    const float f1 = g_f1[(h*BB + b)*NN + q];
    const unsigned int* mrow = &g_mask[(b*NN + q)*16];

    unsigned long long acc[FH/2];
#pragma unroll
    for (int i = 0; i < FH/2; i++) acc[i] = 0ull;
    float m = NEGINF, l = 0.f;

    for (int j0 = 0; j0 < NN; j0 += JB){
        __syncthreads();
        // load key tile: 128 rows x 16 float4 = 2048 float4
        const float4* src = (const float4*)&g_hfeat[(size_t)(b*NN + j0)*FC + h*FH];
#pragma unroll
        for (int i = 0; i < 8; i++){
            int lin = tid + i*256;
            int jj = lin >> 4;
            int o4 = lin & 15;
            float4 v = src[(size_t)jj*(FC/4) + o4];
            ((float4*)&hs[jj][0])[o4] = v;
        }
        if (tid < JB) f2s[tid] = g_f2[(h*BB + b)*NN + j0 + tid];
        __syncthreads();

        uint4 mw4 = *(const uint4*)&mrow[j0 >> 5];
        unsigned int mwa[4] = {mw4.x, mw4.y, mw4.z, mw4.w};

        // ---- pass 1: block max of f2 over unmasked (leaky is monotone) ----
        float mx = -3.0e38f;
#pragma unroll
        for (int wi = 0; wi < 4; wi++){
            unsigned int w = mwa[wi];
#pragma unroll 8
            for (int t = 0; t < 32; t++){
                float v = f2s[wi*32 + t];
                if ((w >> t) & 1) mx = fmaxf(mx, v);
            }
        }
        float bm = f1 + mx;
        bm = fmaxf(bm, LALPHA * bm);            // leaky_relu
        float mn = fmaxf(m, bm);
        float scale = __expf(m - mn);
        l *= scale;
        unsigned long long s2p = pack2(scale, scale);
#pragma unroll
        for (int i = 0; i < FH/2; i++) acc[i] = mul2(acc[i], s2p);
        m = mn;

        // ---- pass 2: accumulate ----
#pragma unroll
        for (int wi = 0; wi < 4; wi++){
            unsigned int w = mwa[wi];
#pragma unroll 2
            for (int t = 0; t < 32; t++){
                int jj = wi*32 + t;
                float e = f1 + f2s[jj];
                e = fmaxf(e, LALPHA * e);
                e = ((w >> t) & 1) ? e : NEGINF;
                float p = __expf(e - m);
                l += p;
                unsigned long long pp = pack2(p, p);
                const ulonglong2* hrow = (const ulonglong2*)&hs[jj][0];
#pragma unroll
                for (int i = 0; i < FH/4; i++){
                    ulonglong2 hv = hrow[i];
                    acc[2*i]   = fma2(pp, hv.x, acc[2*i]);
                    acc[2*i+1] = fma2(pp, hv.y, acc[2*i+1]);
                }
            }
        }
    }

    // epilogue: normalize + ELU, write x_cat
    float rl = 1.0f / l;
    float* outp = &g_xcat[(size_t)(b*NN + q)*FC + h*FH];
#pragma unroll
    for (int i = 0; i < FH/2; i += 2){
        float2 v0 = unpack2(acc[i]);
        float2 v1 = unpack2(acc[i+1]);
        float4 o4;
        float a;
        a = v0.x * rl; o4.x = (a > 0.f) ? a : expm1f(a);
        a = v0.y * rl; o4.y = (a > 0.f) ? a : expm1f(a);
        a = v1.x * rl; o4.z = (a > 0.f) ? a : expm1f(a);
        a = v1.y * rl; o4.w = (a > 0.f) ? a : expm1f(a);
        ((float4*)outp)[i >> 1] = o4;
    }
}

// ---------------- kernel 5: layer2 projection + f1b/f2b ------------------------
// h2 = x_cat @ W_out  (16384 x 512 x 16);  64 rows/CTA, thread = (row, col-quad)
__global__ __launch_bounds__(256) void proj2_kernel(const float* __restrict__ Wout,
                                                    const float* __restrict__ a1o,
                                                    const float* __restrict__ a2o){
    __shared__ float4 ws[FC][4];   // [k][cq] = W[k][4cq..4cq+3]
    const int tid = threadIdx.x;
#pragma unroll
    for (int i = 0; i < 8; i++)
        ((float4*)ws)[tid + i*256] = ((const float4*)Wout)[tid + i*256];
    __syncthreads();

    const int r  = tid >> 2;
    const int cq = tid & 3;
    const int row = blockIdx.x * 64 + r;
    const float4* xr = (const float4*)&g_xcat[(size_t)row*FC];

    float4 acc = make_float4(0.f, 0.f, 0.f, 0.f);
#pragma unroll 4
    for (int k4 = 0; k4 < FC/4; k4++){
        float4 xv = xr[k4];
        float4 w;
        w = ws[4*k4+0][cq];
        acc.x = fmaf(xv.x, w.x, acc.x); acc.y = fmaf(xv.x, w.y, acc.y);
        acc.z = fmaf(xv.x, w.z, acc.z); acc.w = fmaf(xv.x, w.w, acc.w);
        w = ws[4*k4+1][cq];
        acc.x = fmaf(xv.y, w.x, acc.x); acc.y = fmaf(xv.y, w.y, acc.y);
        acc.z = fmaf(xv.y, w.z, acc.z); acc.w = fmaf(xv.y, w.w, acc.w);
        w = ws[4*k4+2][cq];
        acc.x = fmaf(xv.z, w.x, acc.x); acc.y = fmaf(xv.z, w.y, acc.y);
        acc.z = fmaf(xv.z, w.z, acc.z); acc.w = fmaf(xv.z, w.w, acc.w);
        w = ws[4*k4+3][cq];
        acc.x = fmaf(xv.w, w.x, acc.x); acc.y = fmaf(xv.w, w.y, acc.y);
        acc.z = fmaf(xv.w, w.z, acc.z); acc.w = fmaf(xv.w, w.w, acc.w);
    }

    // score partials over this thread's 4 cols
    float s1 = acc.x*a1o[cq*4] + acc.y*a1o[cq*4+1] + acc.z*a1o[cq*4+2] + acc.w*a1o[cq*4+3];
    float s2 = acc.x*a2o[cq*4] + acc.y*a2o[cq*4+1] + acc.z*a2o[cq*4+2] + acc.w*a2o[cq*4+3];
    s1 += __shfl_xor_sync(0xffffffffu, s1, 1);
    s1 += __shfl_xor_sync(0xffffffffu, s1, 2);
    s2 += __shfl_xor_sync(0xffffffffu, s2, 1);
    s2 += __shfl_xor_sync(0xffffffffu, s2, 2);

    *(float4*)&g_h2[(size_t)row*CC + cq*4] = acc;
    if (cq == 0){ g_f1b[row] = s1; g_f2b[row] = s2; }
}

// ---------------- kernel 6: layer2 attention (no ELU), writes d_out ------------
__global__ __launch_bounds__(128) void attn2_kernel(float* __restrict__ out){
    __shared__ unsigned long long hs[JB][CC/2];
    __shared__ float f2s[JB];
    const int tid = threadIdx.x;
    const int b = blockIdx.y;
    const int q = blockIdx.x * 128 + tid;

    const float f1 = g_f1b[b*NN + q];
    const unsigned int* mrow = &g_mask[(b*NN + q)*16];

    unsigned long long acc[CC/2];
#pragma unroll
    for (int i = 0; i < CC/2; i++) acc[i] = 0ull;
    float m = NEGINF, l = 0.f;

    for (int j0 = 0; j0 < NN; j0 += JB){
        __syncthreads();
#pragma unroll
        for (int i = 0; i < 4; i++){
            int lin = tid + i*128;     // 0..511
            int jj = lin >> 2;
            int o4 = lin & 3;
            float4 v = *(const float4*)&g_h2[(size_t)(b*NN + j0 + jj)*CC + o4*4];
            ((float4*)&hs[jj][0])[o4] = v;
        }
        f2s[tid] = g_f2b[b*NN + j0 + tid];
        __syncthreads();

        uint4 mw4 = *(const uint4*)&mrow[j0 >> 5];
        unsigned int mwa[4] = {mw4.x, mw4.y, mw4.z, mw4.w};

        float mx = -3.0e38f;
#pragma unroll
        for (int wi = 0; wi < 4; wi++){
            unsigned int w = mwa[wi];
#pragma unroll 8
            for (int t = 0; t < 32; t++){
                float v = f2s[wi*32 + t];
                if ((w >> t) & 1) mx = fmaxf(mx, v);
            }
        }
        float bm = f1 + mx;
        bm = fmaxf(bm, LALPHA * bm);
        float mn = fmaxf(m, bm);
        float scale = __expf(m - mn);
        l *= scale;
        unsigned long long s2p = pack2(scale, scale);
#pragma unroll
        for (int i = 0; i < CC/2; i++) acc[i] = mul2(acc[i], s2p);
        m = mn;

#pragma unroll
        for (int wi = 0; wi < 4; wi++){
            unsigned int w = mwa[wi];
#pragma unroll 4
            for (int t = 0; t < 32; t++){
                int jj = wi*32 + t;
                float e = f1 + f2s[jj];
                e = fmaxf(e, LALPHA * e);
                e = ((w >> t) & 1) ? e : NEGINF;
                float p = __expf(e - m);
                l += p;
                unsigned long long pp = pack2(p, p);
                const ulonglong2* hrow = (const ulonglong2*)&hs[jj][0];
#pragma unroll
                for (int i = 0; i < CC/4; i++){
                    ulonglong2 hv = hrow[i];
                    acc[2*i]   = fma2(pp, hv.x, acc[2*i]);
                    acc[2*i+1] = fma2(pp, hv.y, acc[2*i+1]);
                }
            }
        }
    }

    float rl = 1.0f / l;
    float* op = &out[(size_t)(b*NN + q)*CC];
#pragma unroll
    for (int i = 0; i < CC/2; i += 2){
        float2 v0 = unpack2(acc[i]);
        float2 v1 = unpack2(acc[i+1]);
        float4 o4 = make_float4(v0.x*rl, v0.y*rl, v1.x*rl, v1.y*rl);
        ((float4*)op)[i >> 1] = o4;
    }
}

// ---------------- launch --------------------------------------------------------
extern "C" void kernel_launch(void* const* d_in, const int* in_sizes, int n_in,
                              void* d_out, int out_size){
    const float* x   = (const float*)d_in[0];
    const int*   adj = (const int*)  d_in[1];
    const float* Wh  = (const float*)d_in[2];
    const float* a1h = (const float*)d_in[3];
    const float* a2h = (const float*)d_in[4];
    const float* Wo  = (const float*)d_in[5];
    const float* a1o = (const float*)d_in[6];
    const float* a2o = (const float*)d_in[7];
    float* out = (float*)d_out;

    pack_mask_kernel<<<32768, 256>>>(adj);
    proj1_kernel<<<dim3(128, NH), 256>>>(x, Wh);
    fvec1_kernel<<<512, 256>>>(a1h, a2h);
    attn1_kernel<<<dim3(NN/256, BB, NH), 256>>>();
    proj2_kernel<<<BB*NN/64, 256>>>(Wo, a1o, a2o);
    attn2_kernel<<<dim3(NN/128, BB), 128>>>(out);
}